// round 16
// baseline (speedup 1.0000x reference)
#include <cuda_runtime.h>
#include <math.h>

#define BB 8
#define CC 64
#define HH 128
#define WW 128
#define HW (HH*WW)
#define MX 32
#define MY 17
#define MXY (MX*MY)
#define NPS 10000
#define NPF 5000
#define EDS 64
#define EDF 32
#define NH 4
#define OPH 16
#define SPART 100
#define SPN 100

#define MLP_SMEM ((8192 + 4096 + 8192 + 4096)*4)   /* 98304 B */
#define FWD_SMEM (32768 + 17408 + 1024 + 1024)     /* 52224 B; red aliases xs */

typedef unsigned long long ull;
__device__ __forceinline__ ull pk(float x, float y){
    ull r; asm("mov.b64 %0, {%1,%2};" : "=l"(r) : "f"(x), "f"(y)); return r;
}
__device__ __forceinline__ void upk(ull v, float& x, float& y){
    asm("mov.b64 {%0,%1}, %2;" : "=f"(x), "=f"(y) : "l"(v));
}
__device__ __forceinline__ ull ffma2(ull a, ull b, ull c){
    ull d; asm("fma.rn.f32x2 %0, %1, %2, %3;" : "=l"(d) : "l"(a), "l"(b), "l"(c)); return d;
}

// ---------------- scratch (static device globals; no runtime alloc) ----------
// g_hist zero-invariant: .bss zero at load; k_y re-zeroes after each use.
__device__ float  g_table[NPS*CC];
__device__ int    g_idx[BB*HW];
__device__ int    g_hist[BB*NPS];
__device__ float2 g_lo[BB*CC*MXY];
__device__ double g_magpart[BB*CC];
__device__ float  g_spart[BB*SPART*CC];
__device__ float  g_mhfm[BB*CC];
__device__ float  g_specm[BB*CC];
__device__ float  g_mhf[BB*CC*HW];
__device__ float  g_spec[BB*CC*HW];
__device__ float  g_y[BB*CC*HW];
__device__ double g_ysum[BB];
__device__ double g_ysq[BB];
__device__ float  g_gw[BB*3];

// ============================================================================
// MEGA1: blocks [0,512) forward DFT | [512,1024) hash | [1024,1649) table
// ============================================================================
__global__ void k_mega1(const float* __restrict__ x,
                        const float* __restrict__ se_emb,
                        const float* __restrict__ se_w,
                        const float* __restrict__ se_b) {
    extern __shared__ float sm[];
    int bx = blockIdx.x;
    int tid = threadIdx.x;

    if (bx >= 1024) {
        // ---- table: t in [0, NPS*16) ----
        int t = (bx - 1024)*256 + tid;
        if (t < BB) { g_ysum[t] = 0.0; g_ysq[t] = 0.0; }
        if (t >= NPS*16) return;
        int cg = t & 15, p = t >> 4;
        float4 acc = *(const float4*)(se_b + cg*4);
        const float* er = se_emb + p*EDS;
        #pragma unroll 8
        for (int e = 0; e < EDS; e++) {
            float ev = er[e];
            float4 wv = __ldg((const float4*)(se_w + e*CC + cg*4));
            acc.x += ev*wv.x; acc.y += ev*wv.y; acc.z += ev*wv.z; acc.w += ev*wv.w;
        }
        *(float4*)(g_table + p*CC + cg*4) = acc;
        return;
    }

    if (bx >= 512) {
        // ---- hash: 512 blocks x 2 rows; sub-row = tid>>7 ----
        int hb = bx - 512;
        int b = hb >> 6, sub = tid >> 7, w = tid & 127;
        int h = (hb & 63)*2 + sub;
        int hm = max(h-1, 0), hp = min(h+1, HH-1);
        int wm = max(w-1, 0), wp = min(w+1, WW-1);
        int* sv = (int*)sm + sub*512;        // [4][128] per sub-row
        const float* xb = x + (size_t)b*CC*HW;
        float acc = 0.f;
        for (int c = 0; c < CC; c += 4) {
            const float* xc = xb + c*HW;
            int V0 = (int)(xc[hm*WW + w]*100.0f) + (int)(xc[h*WW + w]*100.0f) + (int)(xc[hp*WW + w]*100.0f);
            xc += HW;
            int V1 = (int)(xc[hm*WW + w]*100.0f) + (int)(xc[h*WW + w]*100.0f) + (int)(xc[hp*WW + w]*100.0f);
            xc += HW;
            int V2 = (int)(xc[hm*WW + w]*100.0f) + (int)(xc[h*WW + w]*100.0f) + (int)(xc[hp*WW + w]*100.0f);
            xc += HW;
            int V3 = (int)(xc[hm*WW + w]*100.0f) + (int)(xc[h*WW + w]*100.0f) + (int)(xc[hp*WW + w]*100.0f);
            __syncthreads();
            sv[0*128 + w] = V0; sv[1*128 + w] = V1; sv[2*128 + w] = V2; sv[3*128 + w] = V3;
            __syncthreads();
            int h0 = sv[0*128 + wm] + sv[0*128 + w] + sv[0*128 + wp];
            int h1 = sv[1*128 + wm] + sv[1*128 + w] + sv[1*128 + wp];
            int h2 = sv[2*128 + wm] + sv[2*128 + w] + sv[2*128 + wp];
            int h3 = sv[3*128 + wm] + sv[3*128 + w] + sv[3*128 + wp];
            acc += (float)(abs(h0) % NPS) + (float)(abs(h1) % NPS)
                 + (float)(abs(h2) % NPS) + (float)(abs(h3) % NPS);
        }
        int idx = (int)(acc * 0.015625f);
        g_idx[b*HW + h*WW + w] = idx;
        atomicAdd(&g_hist[b*NPS + idx], 1);
        return;
    }

    // ---- forward DFT (bc = bx) ----
    float*  xs  = sm;                        // 64*128 rotated tile chunk
    float2* T   = (float2*)(sm + 8192);      // 128*17
    float2* twp = T + 2176;                  // (cos, sin)
    float2* twm = twp + 128;                 // (cos, -sin)
    double* red = (double*)sm;               // aliases xs (dead by reduction)

    int bc = bx;
    for (int t = tid; t < 128; t += 256) {
        float s, c; sincospif(t * (1.0f/64.0f), &s, &c);
        twp[t] = make_float2(c, s);
        twm[t] = make_float2(c, -s);
    }
    __syncthreads();
    const float* xp = x + (size_t)bc*HW;
    int r = tid & 63, q = tid >> 6;
    int k0 = (q == 0) ? 0 : (4*q + 1);

    for (int chunk = 0; chunk < 2; chunk++) {
        for (int o = tid; o < 8192; o += 256) {
            int rr = o >> 7, w = o & 127;
            xs[rr*128 + ((w + rr) & 127)] = xp[(size_t)(chunk*64 + rr)*WW + w];
        }
        __syncthreads();
        float x0  = xs[r*128 + (r & 127)];
        float x64 = xs[r*128 + ((64 + r) & 127)];
        ull a0 = 0, a1 = 0, a2 = 0, a3 = 0, a4 = 0;
        int i0 = k0, i1 = k0+1, i2 = k0+2, i3 = k0+3, i4 = 4;
        for (int w = 1; w < 64; w++) {
            float v1 = xs[r*128 + ((w + r) & 127)];
            float v2 = xs[r*128 + ((128 - w + r) & 127)];
            ull ab = pk(v1 + v2, v1 - v2);
            float2 e;
            e = twm[i0]; a0 = ffma2(ab, pk(e.x, e.y), a0); i0 = (i0 + k0)     & 127;
            e = twm[i1]; a1 = ffma2(ab, pk(e.x, e.y), a1); i1 = (i1 + k0 + 1) & 127;
            e = twm[i2]; a2 = ffma2(ab, pk(e.x, e.y), a2); i2 = (i2 + k0 + 2) & 127;
            e = twm[i3]; a3 = ffma2(ab, pk(e.x, e.y), a3); i3 = (i3 + k0 + 3) & 127;
            if (q == 0) { e = twm[i4]; a4 = ffma2(ab, pk(e.x, e.y), a4); i4 = (i4 + 4) & 127; }
        }
        int h = chunk*64 + r;
        float cr, ci;
        upk(a0, cr, ci); cr += x0 + (((k0  )&1) ? -x64 : x64); T[h*17 + k0    ] = make_float2(cr, ci);
        upk(a1, cr, ci); cr += x0 + (((k0+1)&1) ? -x64 : x64); T[h*17 + k0 + 1] = make_float2(cr, ci);
        upk(a2, cr, ci); cr += x0 + (((k0+2)&1) ? -x64 : x64); T[h*17 + k0 + 2] = make_float2(cr, ci);
        upk(a3, cr, ci); cr += x0 + (((k0+3)&1) ? -x64 : x64); T[h*17 + k0 + 3] = make_float2(cr, ci);
        if (q == 0) { upk(a4, cr, ci); cr += x0 + x64; T[h*17 + 4] = make_float2(cr, ci); }
        __syncthreads();
    }

    float msum = 0.f;
    if (tid < 136) {
        int kxg = tid / 17, ky = tid % 17;
        int kx0 = kxg*4;
        ull P0=0,Q0=0,P1=0,Q1=0,P2=0,Q2=0,P3=0,Q3=0;
        int i0 = 0, i1 = 0, i2 = 0, i3 = 0;
        for (int h = 0; h < 64; h++) {
            float2 t1 = T[h*17 + ky];
            float2 t2 = T[(h+64)*17 + ky];
            ull SPx = pk(t1.x + t2.x, t1.x + t2.x);
            ull SPy = pk(t1.y + t2.y, t1.y + t2.y);
            ull SMx = pk(t1.x - t2.x, t1.x - t2.x);
            ull SMy = pk(t1.y - t2.y, t1.y - t2.y);
            float2 e;
            e = twp[i0]; i0 = (i0 + kx0    ) & 127; { ull ev = pk(e.x,e.y); P0 = ffma2(SPx, ev, P0); Q0 = ffma2(SPy, ev, Q0); }
            e = twp[i1]; i1 = (i1 + kx0 + 1) & 127; { ull ev = pk(e.x,e.y); P1 = ffma2(SMx, ev, P1); Q1 = ffma2(SMy, ev, Q1); }
            e = twp[i2]; i2 = (i2 + kx0 + 2) & 127; { ull ev = pk(e.x,e.y); P2 = ffma2(SPx, ev, P2); Q2 = ffma2(SPy, ev, Q2); }
            e = twp[i3]; i3 = (i3 + kx0 + 3) & 127; { ull ev = pk(e.x,e.y); P3 = ffma2(SMx, ev, P3); Q3 = ffma2(SMy, ev, Q3); }
        }
        float px, py, qx, qy, a, bb;
        #define FWD_EMIT(Pu, Qu, U) \
            upk(Pu, px, py); upk(Qu, qx, qy); \
            a = (px + qy)*0.0078125f; bb = (qx - py)*0.0078125f; \
            g_lo[bc*MXY + (kx0 + U)*17 + ky] = make_float2(a, bb); \
            msum += sqrtf(a*a + bb*bb);
        FWD_EMIT(P0, Q0, 0)
        FWD_EMIT(P1, Q1, 1)
        FWD_EMIT(P2, Q2, 2)
        FWD_EMIT(P3, Q3, 3)
        #undef FWD_EMIT
    }
    __syncthreads();                 // T reads done; xs/red region reusable
    red[tid] = (double)msum; __syncthreads();
    for (int s = 128; s > 0; s >>= 1) {
        if (tid < s) red[tid] += red[tid+s];
        __syncthreads();
    }
    if (tid == 0) g_magpart[bc] = red[0];
}

// ============================================================================
// MEGA2: blocks [0,512) coef | [512,1312) spatial-mean partials
// ============================================================================
__global__ void k_mega2(const float* __restrict__ wr, const float* __restrict__ wi,
                        const float* __restrict__ mhf_bias,
                        const float* __restrict__ sp_emb,
                        const float* __restrict__ sp_wr, const float* __restrict__ sp_br,
                        const float* __restrict__ sp_wi, const float* __restrict__ sp_bi) {
    __shared__ float2 Fm[MXY], Fs[MXY];
    __shared__ __align__(16) float2 Gm[128*18], Gs[128*18];
    __shared__ float2 twp[128];
    __shared__ float fes[EDF];
    __shared__ int s_fidx;
    __shared__ float4 red4[256];
    int bx = blockIdx.x;
    int tid = threadIdx.x;

    if (bx >= 512) {
        // ---- spat partials: bp = (b, part) of 100 rows ----
        int bp = bx - 512;
        int b = bp / SPART, part = bp % SPART;
        int c4 = tid & 15, rep = tid >> 4;
        int n0 = part*SPN;
        float4 acc = make_float4(0.f, 0.f, 0.f, 0.f);
        const int* hb = g_hist + b*NPS;
        const float4* tb4 = (const float4*)g_table;
        for (int n = n0 + rep; n < n0 + SPN; n += 16) {
            int hv = hb[n];
            if (hv) {
                float fh = (float)hv;
                float4 tv = tb4[n*16 + c4];
                acc.x += fh*tv.x; acc.y += fh*tv.y; acc.z += fh*tv.z; acc.w += fh*tv.w;
            }
        }
        red4[tid] = acc; __syncthreads();
        if (tid < 16) {
            float4 s = make_float4(0.f, 0.f, 0.f, 0.f);
            #pragma unroll
            for (int rp = 0; rp < 16; rp++) {
                float4 v = red4[rp*16 + tid];
                s.x += v.x; s.y += v.y; s.z += v.z; s.w += v.w;
            }
            ((float4*)g_spart)[(b*SPART + part)*16 + tid] = s;
        }
        return;
    }

    // ---- coef (bc = bx) ----
    int bc = bx; int b = bc >> 6, c = bc & 63;
    int hc = c >> 4, oc = c & 15;
    for (int t = tid; t < 128; t += 256) {
        float s, co; sincospif(t * (1.0f/64.0f), &s, &co);
        twp[t] = make_float2(co, s);
    }
    if (tid == 0) {
        double msum = 0.0;
        const double* mp = g_magpart + b*CC;
        for (int i = 0; i < CC; i++) msum += mp[i];
        float mag = (float)(msum / (double)(CC*MXY));
        s_fidx = ((int)(mag * 1000.0f)) % NPF;
    }
    __syncthreads();
    if (tid < EDF) fes[tid] = sp_emb[s_fidx*EDF + tid];
    __syncthreads();

    // phase 1: F coefficients
    const float2* lob = g_lo + b*CC*MXY;
    const float* wrb = wr + (size_t)(hc*CC*OPH + oc)*MXY;
    const float* wib = wi + (size_t)(hc*CC*OPH + oc)*MXY;
    for (int o = tid; o < MXY; o += 256) {
        float mr = 0.f, mi = 0.f;
        for (int i = 0; i < CC; i++) {
            float2 l = lob[i*MXY + o];
            float a = wrb[(size_t)i*OPH*MXY + o];
            float bb = wib[(size_t)i*OPH*MXY + o];
            mr += l.x*a - l.y*bb;
            mi += l.x*bb + l.y*a;
        }
        Fm[o] = make_float2(mr, mi);
        float sr = sp_br[c*MXY + o], si = sp_bi[c*MXY + o];
        for (int e = 0; e < EDF; e++) {
            float f = fes[e];
            sr += f * sp_wr[(size_t)e*(CC*MXY) + c*MXY + o];
            si += f * sp_wi[(size_t)e*(CC*MXY) + c*MXY + o];
        }
        Fs[o] = make_float2(sr, si);
        if (o == 0) {
            g_mhfm[bc]  = mr * 0.0078125f + mhf_bias[c];
            g_specm[bc] = sr * 0.0078125f;
        }
    }
    __syncthreads();

    // stage G folded
    for (int o = tid; o < 33*17; o += 256) {
        int h = o/17, ky = o%17;
        ull Pme=0,Qme=0,Pmo=0,Qmo=0, Pse=0,Qse=0,Pso=0,Qso=0;
        int ti = 0;
        #pragma unroll 4
        for (int kx = 0; kx < MX; kx += 2) {
            {
                float2 e = twp[ti]; ti = (ti + h) & 127;
                ull ev = pk(e.x, e.y);
                float2 fm = Fm[kx*17 + ky], fs = Fs[kx*17 + ky];
                Pme = ffma2(pk(fm.x, fm.x), ev, Pme);
                Qme = ffma2(pk(fm.y, fm.y), ev, Qme);
                Pse = ffma2(pk(fs.x, fs.x), ev, Pse);
                Qse = ffma2(pk(fs.y, fs.y), ev, Qse);
            }
            {
                float2 e = twp[ti]; ti = (ti + h) & 127;
                ull ev = pk(e.x, e.y);
                float2 fm = Fm[(kx+1)*17 + ky], fs = Fs[(kx+1)*17 + ky];
                Pmo = ffma2(pk(fm.x, fm.x), ev, Pmo);
                Qmo = ffma2(pk(fm.y, fm.y), ev, Qmo);
                Pso = ffma2(pk(fs.x, fs.x), ev, Pso);
                Qso = ffma2(pk(fs.y, fs.y), ev, Qso);
            }
        }
        int slot = (ky & 1) ? (10 + (ky >> 1)) : (ky >> 1);
        float pex,pey,qex,qey,pox,poy,qox,qoy;
        #define G_EMIT(G, Pe, Qe, Po, Qo) \
            upk(Pe,pex,pey); upk(Qe,qex,qey); upk(Po,pox,poy); upk(Qo,qox,qoy); \
            { float Px=pex+pox, Py=pey+poy, Qx=qex+qox, Qy=qey+qoy; \
              float Mx=pex-pox, My=pey-poy, Nx=qex-qox, Ny=qey-qoy; \
              G[h*18 + slot]        = make_float2(Px - Qy, Py + Qx); \
              G[(h+64)*18 + slot]   = make_float2(Mx - Ny, My + Nx); \
              if (h) { \
                G[(128-h)*18 + slot] = make_float2(Px + Qy, Qx - Py); \
                G[(64-h)*18 + slot]  = make_float2(Mx + Ny, Nx - My); \
              } }
        G_EMIT(Gm, Pme, Qme, Pmo, Qmo)
        G_EMIT(Gs, Pse, Qse, Pso, Qso)
        #undef G_EMIT
    }
    __syncthreads();

    // stage B folded
    float bias = mhf_bias[c];
    const float sc = 0.0078125f;
    float* mout = g_mhf  + (size_t)bc*HW;
    float* sout = g_spec + (size_t)bc*HW;
    {
        int w = tid & 31;
        int hg = tid >> 5;
        ull cse[9], cso[8];
        cse[0] = pk(1.f, 0.f);
        #pragma unroll
        for (int j = 1; j < 9; j++) {
            float2 e = twp[(2*j*w) & 127];
            cse[j] = pk(2.f*e.x, 2.f*e.y);
        }
        #pragma unroll
        for (int j = 0; j < 8; j++) {
            float2 e = twp[((2*j+1)*w) & 127];
            cso[j] = pk(2.f*e.x, 2.f*e.y);
        }
        for (int i = 0; i < 16; i++) {
            int h = hg*16 + i;
            const float4* Ge4m = (const float4*)(Gm + h*18);
            const float4* Go4m = (const float4*)(Gm + h*18 + 10);
            const float4* Ge4s = (const float4*)(Gs + h*18);
            const float4* Go4s = (const float4*)(Gs + h*18 + 10);
            ull me = 0, mo = 0, se = 0, so = 0;
            #pragma unroll
            for (int j2 = 0; j2 < 4; j2++) {
                float4 g = Ge4m[j2];
                me = ffma2(pk(g.x,g.y), cse[2*j2],   me);
                me = ffma2(pk(g.z,g.w), cse[2*j2+1], me);
                float4 s4 = Ge4s[j2];
                se = ffma2(pk(s4.x,s4.y), cse[2*j2],   se);
                se = ffma2(pk(s4.z,s4.w), cse[2*j2+1], se);
            }
            { float2 g = Gm[h*18 + 8]; me = ffma2(pk(g.x,g.y), cse[8], me);
              float2 s2 = Gs[h*18 + 8]; se = ffma2(pk(s2.x,s2.y), cse[8], se); }
            #pragma unroll
            for (int j2 = 0; j2 < 4; j2++) {
                float4 g = Go4m[j2];
                mo = ffma2(pk(g.x,g.y), cso[2*j2],   mo);
                mo = ffma2(pk(g.z,g.w), cso[2*j2+1], mo);
                float4 s4 = Go4s[j2];
                so = ffma2(pk(s4.x,s4.y), cso[2*j2],   so);
                so = ffma2(pk(s4.z,s4.w), cso[2*j2+1], so);
            }
            float Ae,Be,Ao,Bo;
            upk(me,Ae,Be); upk(mo,Ao,Bo);
            {
                float ap=Ae+Ao, bp=Be+Bo, am=Ae-Ao, bm=Be-Bo;
                mout[h*WW + w]        = (ap - bp)*sc + bias;
                mout[h*WW + 64 + w]   = (am - bm)*sc + bias;
                if (w) {
                    mout[h*WW + 128 - w] = (ap + bp)*sc + bias;
                    mout[h*WW + 64 - w]  = (am + bm)*sc + bias;
                }
            }
            upk(se,Ae,Be); upk(so,Ao,Bo);
            {
                float ap=Ae+Ao, bp=Be+Bo, am=Ae-Ao, bm=Be-Bo;
                sout[h*WW + w]        = (ap - bp)*sc;
                sout[h*WW + 64 + w]   = (am - bm)*sc;
                if (w) {
                    sout[h*WW + 128 - w] = (ap + bp)*sc;
                    sout[h*WW + 64 - w]  = (am + bm)*sc;
                }
            }
        }
    }
    // w = 32 orbit {32, 96}
    if (tid < 128) {
        int h = tid;
        ull cse[9], cso[8];
        cse[0] = pk(1.f, 0.f);
        #pragma unroll
        for (int j = 1; j < 9; j++) {
            float2 e = twp[(2*j*32) & 127];
            cse[j] = pk(2.f*e.x, 2.f*e.y);
        }
        #pragma unroll
        for (int j = 0; j < 8; j++) {
            float2 e = twp[((2*j+1)*32) & 127];
            cso[j] = pk(2.f*e.x, 2.f*e.y);
        }
        const float4* Ge4m = (const float4*)(Gm + h*18);
        const float4* Go4m = (const float4*)(Gm + h*18 + 10);
        const float4* Ge4s = (const float4*)(Gs + h*18);
        const float4* Go4s = (const float4*)(Gs + h*18 + 10);
        ull me = 0, mo = 0, se = 0, so = 0;
        #pragma unroll
        for (int j2 = 0; j2 < 4; j2++) {
            float4 g = Ge4m[j2];
            me = ffma2(pk(g.x,g.y), cse[2*j2],   me);
            me = ffma2(pk(g.z,g.w), cse[2*j2+1], me);
            float4 s4 = Ge4s[j2];
            se = ffma2(pk(s4.x,s4.y), cse[2*j2],   se);
            se = ffma2(pk(s4.z,s4.w), cse[2*j2+1], se);
        }
        { float2 g = Gm[h*18 + 8]; me = ffma2(pk(g.x,g.y), cse[8], me);
          float2 s2 = Gs[h*18 + 8]; se = ffma2(pk(s2.x,s2.y), cse[8], se); }
        #pragma unroll
        for (int j2 = 0; j2 < 4; j2++) {
            float4 g = Go4m[j2];
            mo = ffma2(pk(g.x,g.y), cso[2*j2],   mo);
            mo = ffma2(pk(g.z,g.w), cso[2*j2+1], mo);
            float4 s4 = Go4s[j2];
            so = ffma2(pk(s4.x,s4.y), cso[2*j2],   so);
            so = ffma2(pk(s4.z,s4.w), cso[2*j2+1], so);
        }
        float Ae,Be,Ao,Bo;
        upk(me,Ae,Be); upk(mo,Ao,Bo);
        mout[h*WW + 32] = ((Ae+Ao) - (Be+Bo))*sc + bias;
        mout[h*WW + 96] = ((Ae-Ao) - (Be-Bo))*sc + bias;
        upk(se,Ae,Be); upk(so,Ao,Bo);
        sout[h*WW + 32] = ((Ae+Ao) - (Be+Bo))*sc;
        sout[h*WW + 96] = ((Ae-Ao) - (Be-Bo))*sc;
    }
}

__global__ void k_gate(const float* __restrict__ gw1, const float* __restrict__ gb1,
                       const float* __restrict__ gw2, const float* __restrict__ gb2) {
    __shared__ float gi[BB*192];
    __shared__ float h1[BB*64];
    int tid = threadIdx.x;
    for (int o = tid; o < BB*CC; o += 512) {
        int b = o >> 6, c = o & 63;
        float s = 0.f;
        for (int part = 0; part < SPART; part++)
            s += g_spart[(b*SPART + part)*CC + c];
        gi[b*192 + c] = s * (1.0f/16384.0f);
    }
    for (int o = tid; o < BB*128; o += 512) {
        int b = o >> 7, k = o & 127;
        gi[b*192 + 64 + k] = (k < 64) ? g_mhfm[b*64 + k] : g_specm[b*64 + k - 64];
    }
    __syncthreads();
    {
        int b = tid >> 6, j = tid & 63;
        float a = gb1[j];
        for (int k = 0; k < 192; k++) a += gi[b*192 + k] * gw1[k*64 + j];
        h1[tid] = 0.5f*a*(1.0f + erff(a*0.70710678118654752f));
    }
    __syncthreads();
    if (tid < BB) {
        int b = tid;
        float l[3];
        #pragma unroll
        for (int m = 0; m < 3; m++) {
            float a = gb2[m];
            for (int j = 0; j < 64; j++) a += h1[b*64 + j] * gw2[j*3 + m];
            l[m] = a;
        }
        float mx = fmaxf(l[0], fmaxf(l[1], l[2]));
        float e0 = expf(l[0]-mx), e1 = expf(l[1]-mx), e2 = expf(l[2]-mx);
        float inv = 1.0f/(e0+e1+e2);
        g_gw[b*3+0] = e0*inv; g_gw[b*3+1] = e1*inv; g_gw[b*3+2] = e2*inv;
    }
}

// y = gate-weighted fuse + skip conv + skip_b; LN stats; hist re-zero
__global__ void k_y(const float* __restrict__ x,
                    const float* __restrict__ skip_w,
                    const float* __restrict__ skip_b) {
    int bx = blockIdx.x;
    int b = bx >> 8, tile = bx & 255;
    int pbase = tile * 64;
    int tid = threadIdx.x;
    __shared__ float buf[64*65];
    __shared__ float ys[64*64];
    __shared__ int idxs[64];
    __shared__ float red[256], redq[256];

    // re-zero hist for next call (consumed by this call's mega2 already)
    {
        int hz = bx*40 + (tid & 63);
        if (tid < 64 && (tid & 63) < 40 && hz < BB*NPS) g_hist[hz] = 0;
    }
    if (tid >= 64 && tid < 128) idxs[tid - 64] = g_idx[b*HW + pbase + (tid - 64)];
    for (int o = tid; o < 4096; o += 256) {
        int i = o >> 6, p = o & 63;
        buf[i*64 + p] = x[((size_t)(b*64 + i))*HW + pbase + p];
    }
    __syncthreads();
    {
        int pg = tid & 15, cg = tid >> 4;
        ull acc[4][2];
        #pragma unroll
        for (int px = 0; px < 4; px++) { acc[px][0] = 0; acc[px][1] = 0; }
        for (int i = 0; i < 64; i++) {
            float4 xv = *(const float4*)(buf + i*64 + pg*4);
            ull x0 = pk(xv.x, xv.x), x1 = pk(xv.y, xv.y),
                x2 = pk(xv.z, xv.z), x3 = pk(xv.w, xv.w);
            float4 wv = __ldg((const float4*)(skip_w + i*64 + cg*4));
            ull wA = pk(wv.x, wv.y), wB = pk(wv.z, wv.w);
            acc[0][0] = ffma2(x0, wA, acc[0][0]); acc[0][1] = ffma2(x0, wB, acc[0][1]);
            acc[1][0] = ffma2(x1, wA, acc[1][0]); acc[1][1] = ffma2(x1, wB, acc[1][1]);
            acc[2][0] = ffma2(x2, wA, acc[2][0]); acc[2][1] = ffma2(x2, wB, acc[2][1]);
            acc[3][0] = ffma2(x3, wA, acc[3][0]); acc[3][1] = ffma2(x3, wB, acc[3][1]);
        }
        #pragma unroll
        for (int px = 0; px < 4; px++) {
            int p = pg*4 + px;
            #pragma unroll
            for (int u = 0; u < 2; u++) {
                float v0, v1; upk(acc[px][u], v0, v1);
                ys[(cg*4 + 2*u    )*64 + p] = v0;
                ys[(cg*4 + 2*u + 1)*64 + p] = v1;
            }
        }
    }
    __syncthreads();
    for (int o = tid; o < 4096; o += 256) {
        int p = o >> 6, cc2 = o & 63;
        buf[p*65 + cc2] = g_table[idxs[p]*CC + cc2];
    }
    __syncthreads();
    float ga = g_gw[b*3], gbt = g_gw[b*3+1], gm = g_gw[b*3+2];
    float lsum = 0.f, lsq = 0.f;
    for (int o = tid; o < 4096; o += 256) {
        int c = o >> 6, p = o & 63;
        size_t gidx = ((size_t)(b*64 + c))*HW + pbase + p;
        float yv = ga*buf[p*65 + c] + gbt*g_mhf[gidx] + gm*g_spec[gidx]
                 + ys[c*64 + p] + skip_b[c];
        g_y[gidx] = yv;
        lsum += yv; lsq += yv*yv;
    }
    red[tid] = lsum; redq[tid] = lsq; __syncthreads();
    for (int s = 128; s > 0; s >>= 1) {
        if (tid < s) { red[tid] += red[tid+s]; redq[tid] += redq[tid+s]; }
        __syncthreads();
    }
    if (tid == 0) {
        atomicAdd(&g_ysum[b], (double)red[0]);
        atomicAdd(&g_ysq[b],  (double)redq[0]);
    }
}

// layernorm + MLP + residual; y tile staged in smem
__global__ void k_mlp(const float* __restrict__ norm_g, const float* __restrict__ norm_b,
                      const float* __restrict__ w1, const float* __restrict__ b1,
                      const float* __restrict__ w2, const float* __restrict__ b2,
                      float* __restrict__ out) {
    extern __shared__ float sm[];
    float* w12 = sm;                        // 8192
    float* yns = sm + 8192;                 // 4096
    float* hs  = sm + 8192 + 4096;          // 8192
    float* yt  = sm + 8192 + 4096 + 8192;   // 4096: raw y tile
    __shared__ float s_mu, s_rstd;
    int bx = blockIdx.x;
    int b = bx >> 8, tile = bx & 255;
    int pbase = tile * 64;
    int tid = threadIdx.x;

    if (tid == 0) {
        double n = (double)(CC*HW);
        double mu = g_ysum[b] / n;
        double var = g_ysq[b] / n - mu*mu;
        s_mu = (float)mu;
        s_rstd = (float)(1.0 / sqrt(var + 1e-5));
    }
    for (int o = tid; o < 8192; o += 256) w12[o] = w1[o];
    __syncthreads();
    float mu = s_mu, rstd = s_rstd;
    for (int o = tid; o < 4096; o += 256) {
        int c = o >> 6, p = o & 63;
        float yv = g_y[((size_t)(b*64 + c))*HW + pbase + p];
        yt[c*64 + p] = yv;
        yns[c*64 + p] = (yv - mu)*rstd*norm_g[c] + norm_b[c];
    }
    __syncthreads();
    {
        int pg = tid & 15, jg = tid >> 4;
        ull acc[4][4];
        #pragma unroll
        for (int px = 0; px < 4; px++)
            #pragma unroll
            for (int u = 0; u < 4; u++) acc[px][u] = 0;
        for (int c = 0; c < 64; c++) {
            float4 yv4 = *(const float4*)(yns + c*64 + pg*4);
            ull y0 = pk(yv4.x, yv4.x), y1 = pk(yv4.y, yv4.y),
                y2 = pk(yv4.z, yv4.z), y3 = pk(yv4.w, yv4.w);
            const float4* wrow = (const float4*)(w12 + c*128 + jg*8);
            float4 wa = wrow[0], wb = wrow[1];
            ull w0 = pk(wa.x, wa.y), w1p = pk(wa.z, wa.w),
                w2p = pk(wb.x, wb.y), w3 = pk(wb.z, wb.w);
            acc[0][0] = ffma2(y0, w0, acc[0][0]); acc[0][1] = ffma2(y0, w1p, acc[0][1]);
            acc[0][2] = ffma2(y0, w2p, acc[0][2]); acc[0][3] = ffma2(y0, w3, acc[0][3]);
            acc[1][0] = ffma2(y1, w0, acc[1][0]); acc[1][1] = ffma2(y1, w1p, acc[1][1]);
            acc[1][2] = ffma2(y1, w2p, acc[1][2]); acc[1][3] = ffma2(y1, w3, acc[1][3]);
            acc[2][0] = ffma2(y2, w0, acc[2][0]); acc[2][1] = ffma2(y2, w1p, acc[2][1]);
            acc[2][2] = ffma2(y2, w2p, acc[2][2]); acc[2][3] = ffma2(y2, w3, acc[2][3]);
            acc[3][0] = ffma2(y3, w0, acc[3][0]); acc[3][1] = ffma2(y3, w1p, acc[3][1]);
            acc[3][2] = ffma2(y3, w2p, acc[3][2]); acc[3][3] = ffma2(y3, w3, acc[3][3]);
        }
        int j0 = jg*8;
        #pragma unroll
        for (int px = 0; px < 4; px++) {
            int p = pg*4 + px;
            #pragma unroll
            for (int u = 0; u < 4; u++) {
                float v0, v1; upk(acc[px][u], v0, v1);
                int j = j0 + 2*u;
                float a0 = v0 + b1[j], a1 = v1 + b1[j+1];
                hs[j*64 + p]     = 0.5f*a0*(1.0f + erff(a0*0.70710678118654752f));
                hs[(j+1)*64 + p] = 0.5f*a1*(1.0f + erff(a1*0.70710678118654752f));
            }
        }
    }
    __syncthreads();
    for (int o = tid; o < 8192; o += 256) w12[o] = w2[o];
    __syncthreads();
    {
        int pg = tid & 15, cg = tid >> 4;
        ull acc2[4][2];
        #pragma unroll
        for (int px = 0; px < 4; px++) { acc2[px][0] = 0; acc2[px][1] = 0; }
        for (int j = 0; j < 128; j++) {
            float4 hv4 = *(const float4*)(hs + j*64 + pg*4);
            ull h0 = pk(hv4.x, hv4.x), h1 = pk(hv4.y, hv4.y),
                h2 = pk(hv4.z, hv4.z), h3 = pk(hv4.w, hv4.w);
            float4 wv = *(const float4*)(w12 + j*64 + cg*4);
            ull wA = pk(wv.x, wv.y), wB = pk(wv.z, wv.w);
            acc2[0][0] = ffma2(h0, wA, acc2[0][0]); acc2[0][1] = ffma2(h0, wB, acc2[0][1]);
            acc2[1][0] = ffma2(h1, wA, acc2[1][0]); acc2[1][1] = ffma2(h1, wB, acc2[1][1]);
            acc2[2][0] = ffma2(h2, wA, acc2[2][0]); acc2[2][1] = ffma2(h2, wB, acc2[2][1]);
            acc2[3][0] = ffma2(h3, wA, acc2[3][0]); acc2[3][1] = ffma2(h3, wB, acc2[3][1]);
        }
        __syncthreads();
        #pragma unroll
        for (int px = 0; px < 4; px++) {
            int p = pg*4 + px;
            #pragma unroll
            for (int u = 0; u < 2; u++) {
                float v0, v1; upk(acc2[px][u], v0, v1);
                yns[(cg*4 + 2*u    )*64 + p] = v0;
                yns[(cg*4 + 2*u + 1)*64 + p] = v1;
            }
        }
    }
    __syncthreads();
    for (int o = tid; o < 4096; o += 256) {
        int c = o >> 6, p = o & 63;
        size_t gi2 = ((size_t)(b*64 + c))*HW + pbase + p;
        out[gi2] = yt[c*64 + p] + yns[c*64 + p] + b2[c];
    }
}

// ---------------------------------------------------------------------------
extern "C" void kernel_launch(void* const* d_in, const int* in_sizes, int n_in,
                              void* d_out, int out_size) {
    const float* x        = (const float*)d_in[0];
    const float* se_emb   = (const float*)d_in[1];
    const float* se_w     = (const float*)d_in[2];
    const float* se_b     = (const float*)d_in[3];
    const float* mhf_wr   = (const float*)d_in[4];
    const float* mhf_wi   = (const float*)d_in[5];
    const float* mhf_bias = (const float*)d_in[6];
    const float* sp_emb   = (const float*)d_in[7];
    const float* sp_wr    = (const float*)d_in[8];
    const float* sp_br    = (const float*)d_in[9];
    const float* sp_wi    = (const float*)d_in[10];
    const float* sp_bi    = (const float*)d_in[11];
    const float* gate_w1  = (const float*)d_in[12];
    const float* gate_b1  = (const float*)d_in[13];
    const float* gate_w2  = (const float*)d_in[14];
    const float* gate_b2  = (const float*)d_in[15];
    const float* skip_w   = (const float*)d_in[16];
    const float* skip_b   = (const float*)d_in[17];
    const float* norm_g   = (const float*)d_in[18];
    const float* norm_b   = (const float*)d_in[19];
    const float* mlp_w1   = (const float*)d_in[20];
    const float* mlp_b1   = (const float*)d_in[21];
    const float* mlp_w2   = (const float*)d_in[22];
    const float* mlp_b2   = (const float*)d_in[23];
    float* out = (float*)d_out;

    cudaFuncSetAttribute(k_mega1, cudaFuncAttributeMaxDynamicSharedMemorySize, FWD_SMEM);
    cudaFuncSetAttribute(k_mlp,  cudaFuncAttributeMaxDynamicSharedMemorySize, MLP_SMEM);

    k_mega1<<<512 + 512 + 625, 256, FWD_SMEM>>>(x, se_emb, se_w, se_b);
    k_mega2<<<512 + BB*SPART, 256>>>(mhf_wr, mhf_wi, mhf_bias, sp_emb,
                                     sp_wr, sp_br, sp_wi, sp_bi);
    k_gate<<<1, 512>>>(gate_w1, gate_b1, gate_w2, gate_b2);
    k_y<<<BB*256, 256>>>(x, skip_w, skip_b);
    k_mlp<<<BB*256, 256, MLP_SMEM>>>(norm_g, norm_b, mlp_w1, mlp_b1, mlp_w2, mlp_b2, out);
}

// round 17
// speedup vs baseline: 1.0394x; 1.0394x over previous
#include <cuda_runtime.h>
#include <math.h>

#define BB 8
#define CC 64
#define HH 128
#define WW 128
#define HW (HH*WW)
#define MX 32
#define MY 17
#define MXY (MX*MY)
#define NPS 10000
#define NPF 5000
#define EDS 64
#define EDF 32
#define NH 4
#define OPH 16
#define SPART 50
#define SPN 200

#define MLP_SMEM ((8192 + 4096 + 8192 + 4096)*4)   /* 98304 B */
#define FWD_SMEM (32768 + 17408 + 1024 + 1024 + 2048)  /* 54272 B */

typedef unsigned long long ull;
__device__ __forceinline__ ull pk(float x, float y){
    ull r; asm("mov.b64 %0, {%1,%2};" : "=l"(r) : "f"(x), "f"(y)); return r;
}
__device__ __forceinline__ void upk(ull v, float& x, float& y){
    asm("mov.b64 {%0,%1}, %2;" : "=f"(x), "=f"(y) : "l"(v));
}
__device__ __forceinline__ ull ffma2(ull a, ull b, ull c){
    ull d; asm("fma.rn.f32x2 %0, %1, %2, %3;" : "=l"(d) : "l"(a), "l"(b), "l"(c)); return d;
}

// ---------------- scratch (static device globals; no runtime alloc) ----------
__device__ float  g_table[NPS*CC];
__device__ int    g_idx[BB*HW];
__device__ int    g_hist[BB*NPS];
__device__ float2 g_lo[BB*CC*MXY];
__device__ double g_magpart[BB*CC];
__device__ float  g_spart[BB*SPART*CC];
__device__ float  g_mhfm[BB*CC];
__device__ float  g_specm[BB*CC];
__device__ float  g_fused[BB*CC*HW];
__device__ float  g_y[BB*CC*HW];
__device__ double g_ysum[BB];
__device__ double g_ysq[BB];
__device__ float  g_gw[BB*3];

// table[p][c] = sum_e se_emb[p][e]*se_w[e][c] + se_b[c]  (float4, + init fold)
__global__ void k_table(const float* __restrict__ se_emb,
                        const float* __restrict__ se_w,
                        const float* __restrict__ se_b) {
    int t = blockIdx.x*256 + threadIdx.x;     // t < NPS*16
    if (t < BB*NPS) g_hist[t] = 0;
    if (t < BB) { g_ysum[t] = 0.0; g_ysq[t] = 0.0; }
    if (t >= NPS*16) return;
    int cg = t & 15, p = t >> 4;
    float4 acc = *(const float4*)(se_b + cg*4);
    const float* er = se_emb + p*EDS;
    #pragma unroll 8
    for (int e = 0; e < EDS; e++) {
        float ev = er[e];
        float4 wv = __ldg((const float4*)(se_w + e*CC + cg*4));
        acc.x += ev*wv.x; acc.y += ev*wv.y; acc.z += ev*wv.z; acc.w += ev*wv.w;
    }
    *(float4*)(g_table + p*CC + cg*4) = acc;
}

// spatial hash -> idx[b][pix], plus histogram. 4-channel batched staging.
__global__ void k_hash(const float* __restrict__ x) {
    int bid = blockIdx.x;
    int b = bid >> 7, h = bid & 127;
    int w = threadIdx.x;
    int hm = max(h-1, 0), hp = min(h+1, HH-1);
    int wm = max(w-1, 0), wp = min(w+1, WW-1);
    __shared__ int sv[4][128];
    const float* xb = x + (size_t)b*CC*HW;
    float acc = 0.f;
    for (int c = 0; c < CC; c += 4) {
        const float* xc = xb + c*HW;
        int V0 = (int)(xc[hm*WW + w]*100.0f) + (int)(xc[h*WW + w]*100.0f) + (int)(xc[hp*WW + w]*100.0f);
        xc += HW;
        int V1 = (int)(xc[hm*WW + w]*100.0f) + (int)(xc[h*WW + w]*100.0f) + (int)(xc[hp*WW + w]*100.0f);
        xc += HW;
        int V2 = (int)(xc[hm*WW + w]*100.0f) + (int)(xc[h*WW + w]*100.0f) + (int)(xc[hp*WW + w]*100.0f);
        xc += HW;
        int V3 = (int)(xc[hm*WW + w]*100.0f) + (int)(xc[h*WW + w]*100.0f) + (int)(xc[hp*WW + w]*100.0f);
        __syncthreads();
        sv[0][w] = V0; sv[1][w] = V1; sv[2][w] = V2; sv[3][w] = V3;
        __syncthreads();
        int h0 = sv[0][wm] + sv[0][w] + sv[0][wp];
        int h1 = sv[1][wm] + sv[1][w] + sv[1][wp];
        int h2 = sv[2][wm] + sv[2][w] + sv[2][wp];
        int h3 = sv[3][wm] + sv[3][w] + sv[3][wp];
        acc += (float)(abs(h0) % NPS) + (float)(abs(h1) % NPS)
             + (float)(abs(h2) % NPS) + (float)(abs(h3) % NPS);
    }
    int idx = (int)(acc * 0.015625f);
    g_idx[b*HW + h*WW + w] = idx;
    atomicAdd(&g_hist[b*NPS + idx], 1);
}

// spatial-mean partials: block = (b, part); 50 parts x 200 rows.
__global__ void k_spat() {
    int bp = blockIdx.x;
    int b = bp / SPART, part = bp % SPART;
    int tid = threadIdx.x;           // 128
    int c = tid & 63, rep = tid >> 6;
    int n0 = part*SPN;
    float acc = 0.f;
    const int* hb = g_hist + b*NPS;
    for (int n = n0 + rep; n < n0 + SPN; n += 2) {
        int hv = hb[n];
        if (hv) acc += (float)hv * g_table[n*CC + c];
    }
    __shared__ float red[128];
    red[tid] = acc; __syncthreads();
    if (tid < 64)
        g_spart[(b*SPART + part)*CC + c] = red[c] + red[64 + c];
}

// forward low-mode DFT with w<->128-w folding (stage 1) and
// P/Q + h<->h+64 parity folding (stage 2).
__global__ void k_fwd(const float* __restrict__ x) {
    extern __shared__ float sm[];
    float*  xs  = sm;                        // 64*128 rotated tile chunk
    float2* T   = (float2*)(sm + 8192);      // 128*17
    float2* twp = T + 2176;                  // (cos, sin)
    float2* twm = twp + 128;                 // (cos, -sin)
    double* red = (double*)(twm + 128);      // 256

    int bc = blockIdx.x;
    int tid = threadIdx.x;
    for (int t = tid; t < 128; t += 256) {
        float s, c; sincospif(t * (1.0f/64.0f), &s, &c);
        twp[t] = make_float2(c, s);
        twm[t] = make_float2(c, -s);
    }
    __syncthreads();
    const float* xp = x + (size_t)bc*HW;
    int r = tid & 63, q = tid >> 6;
    int k0 = (q == 0) ? 0 : (4*q + 1);

    for (int chunk = 0; chunk < 2; chunk++) {
        for (int o = tid; o < 8192; o += 256) {
            int rr = o >> 7, w = o & 127;
            xs[rr*128 + ((w + rr) & 127)] = xp[(size_t)(chunk*64 + rr)*WW + w];
        }
        __syncthreads();
        float x0  = xs[r*128 + (r & 127)];
        float x64 = xs[r*128 + ((64 + r) & 127)];
        ull a0 = 0, a1 = 0, a2 = 0, a3 = 0, a4 = 0;
        int i0 = k0, i1 = k0+1, i2 = k0+2, i3 = k0+3, i4 = 4;
        for (int w = 1; w < 64; w++) {
            float v1 = xs[r*128 + ((w + r) & 127)];
            float v2 = xs[r*128 + ((128 - w + r) & 127)];
            ull ab = pk(v1 + v2, v1 - v2);
            float2 e;
            e = twm[i0]; a0 = ffma2(ab, pk(e.x, e.y), a0); i0 = (i0 + k0)     & 127;
            e = twm[i1]; a1 = ffma2(ab, pk(e.x, e.y), a1); i1 = (i1 + k0 + 1) & 127;
            e = twm[i2]; a2 = ffma2(ab, pk(e.x, e.y), a2); i2 = (i2 + k0 + 2) & 127;
            e = twm[i3]; a3 = ffma2(ab, pk(e.x, e.y), a3); i3 = (i3 + k0 + 3) & 127;
            if (q == 0) { e = twm[i4]; a4 = ffma2(ab, pk(e.x, e.y), a4); i4 = (i4 + 4) & 127; }
        }
        int h = chunk*64 + r;
        float cr, ci;
        upk(a0, cr, ci); cr += x0 + (((k0  )&1) ? -x64 : x64); T[h*17 + k0    ] = make_float2(cr, ci);
        upk(a1, cr, ci); cr += x0 + (((k0+1)&1) ? -x64 : x64); T[h*17 + k0 + 1] = make_float2(cr, ci);
        upk(a2, cr, ci); cr += x0 + (((k0+2)&1) ? -x64 : x64); T[h*17 + k0 + 2] = make_float2(cr, ci);
        upk(a3, cr, ci); cr += x0 + (((k0+3)&1) ? -x64 : x64); T[h*17 + k0 + 3] = make_float2(cr, ci);
        if (q == 0) { upk(a4, cr, ci); cr += x0 + x64; T[h*17 + 4] = make_float2(cr, ci); }
        __syncthreads();
    }

    float msum = 0.f;
    if (tid < 136) {
        int kxg = tid / 17, ky = tid % 17;
        int kx0 = kxg*4;
        ull P0=0,Q0=0,P1=0,Q1=0,P2=0,Q2=0,P3=0,Q3=0;
        int i0 = 0, i1 = 0, i2 = 0, i3 = 0;
        for (int h = 0; h < 64; h++) {
            float2 t1 = T[h*17 + ky];
            float2 t2 = T[(h+64)*17 + ky];
            ull SPx = pk(t1.x + t2.x, t1.x + t2.x);
            ull SPy = pk(t1.y + t2.y, t1.y + t2.y);
            ull SMx = pk(t1.x - t2.x, t1.x - t2.x);
            ull SMy = pk(t1.y - t2.y, t1.y - t2.y);
            float2 e;
            e = twp[i0]; i0 = (i0 + kx0    ) & 127; { ull ev = pk(e.x,e.y); P0 = ffma2(SPx, ev, P0); Q0 = ffma2(SPy, ev, Q0); }
            e = twp[i1]; i1 = (i1 + kx0 + 1) & 127; { ull ev = pk(e.x,e.y); P1 = ffma2(SMx, ev, P1); Q1 = ffma2(SMy, ev, Q1); }
            e = twp[i2]; i2 = (i2 + kx0 + 2) & 127; { ull ev = pk(e.x,e.y); P2 = ffma2(SPx, ev, P2); Q2 = ffma2(SPy, ev, Q2); }
            e = twp[i3]; i3 = (i3 + kx0 + 3) & 127; { ull ev = pk(e.x,e.y); P3 = ffma2(SMx, ev, P3); Q3 = ffma2(SMy, ev, Q3); }
        }
        float px, py, qx, qy, a, bb;
        #define FWD_EMIT(Pu, Qu, U) \
            upk(Pu, px, py); upk(Qu, qx, qy); \
            a = (px + qy)*0.0078125f; bb = (qx - py)*0.0078125f; \
            g_lo[bc*MXY + (kx0 + U)*17 + ky] = make_float2(a, bb); \
            msum += sqrtf(a*a + bb*bb);
        FWD_EMIT(P0, Q0, 0)
        FWD_EMIT(P1, Q1, 1)
        FWD_EMIT(P2, Q2, 2)
        FWD_EMIT(P3, Q3, 3)
        #undef FWD_EMIT
    }
    red[tid] = (double)msum; __syncthreads();
    for (int s = 128; s > 0; s >>= 1) {
        if (tid < s) red[tid] += red[tid+s];
        __syncthreads();
    }
    if (tid == 0) g_magpart[bc] = red[0];
}

// per (b,c) DC terms for the gate: mhfm / specm  (8 blocks x 64 threads)
__global__ void k_pre(const float* __restrict__ wr, const float* __restrict__ wi,
                      const float* __restrict__ mhf_bias,
                      const float* __restrict__ sp_emb,
                      const float* __restrict__ sp_wr, const float* __restrict__ sp_br) {
    int b = blockIdx.x, c = threadIdx.x;
    int hc = c >> 4, oc = c & 15;
    __shared__ int sfx;
    if (c == 0) {
        double msum = 0.0;
        const double* mp = g_magpart + b*CC;
        for (int i = 0; i < CC; i++) msum += mp[i];
        float mag = (float)(msum / (double)(CC*MXY));
        sfx = ((int)(mag * 1000.0f)) % NPF;
    }
    __syncthreads();
    const float2* lob = g_lo + b*CC*MXY;
    const float* wrb = wr + (size_t)(hc*CC*OPH + oc)*MXY;
    const float* wib = wi + (size_t)(hc*CC*OPH + oc)*MXY;
    float mr = 0.f;
    for (int i = 0; i < CC; i++) {
        float2 l = lob[i*MXY];
        mr += l.x*wrb[(size_t)i*OPH*MXY] - l.y*wib[(size_t)i*OPH*MXY];
    }
    g_mhfm[b*CC + c] = mr * 0.0078125f + mhf_bias[c];
    float sr = sp_br[c*MXY];
    const float* fe = sp_emb + sfx*EDF;
    for (int e = 0; e < EDF; e++)
        sr += fe[e] * sp_wr[(size_t)e*(CC*MXY) + c*MXY];
    g_specm[b*CC + c] = sr * 0.0078125f;
}

__global__ void k_gate(const float* __restrict__ gw1, const float* __restrict__ gb1,
                       const float* __restrict__ gw2, const float* __restrict__ gb2) {
    __shared__ float gi[BB*192];
    __shared__ float h1[BB*64];
    int tid = threadIdx.x;
    for (int o = tid; o < BB*CC; o += 512) {
        int b = o >> 6, c = o & 63;
        float s = 0.f;
        for (int part = 0; part < SPART; part++)
            s += g_spart[(b*SPART + part)*CC + c];
        gi[b*192 + c] = s * (1.0f/16384.0f);
    }
    for (int o = tid; o < BB*128; o += 512) {
        int b = o >> 7, k = o & 127;
        gi[b*192 + 64 + k] = (k < 64) ? g_mhfm[b*64 + k] : g_specm[b*64 + k - 64];
    }
    __syncthreads();
    {
        int b = tid >> 6, j = tid & 63;
        float a = gb1[j];
        for (int k = 0; k < 192; k++) a += gi[b*192 + k] * gw1[k*64 + j];
        h1[tid] = 0.5f*a*(1.0f + erff(a*0.70710678118654752f));
    }
    __syncthreads();
    if (tid < BB) {
        int b = tid;
        float l[3];
        #pragma unroll
        for (int m = 0; m < 3; m++) {
            float a = gb2[m];
            for (int j = 0; j < 64; j++) a += h1[b*64 + j] * gw2[j*3 + m];
            l[m] = a;
        }
        float mx = fmaxf(l[0], fmaxf(l[1], l[2]));
        float e0 = expf(l[0]-mx), e1 = expf(l[1]-mx), e2 = expf(l[2]-mx);
        float inv = 1.0f/(e0+e1+e2);
        g_gw[b*3+0] = e0*inv; g_gw[b*3+1] = e1*inv; g_gw[b*3+2] = e2*inv;
    }
}

// per (b,c): filter + spec coefficients, inverse DFTs, GATED fused output
__global__ void k_coef(const float* __restrict__ wr, const float* __restrict__ wi,
                       const float* __restrict__ mhf_bias,
                       const float* __restrict__ sp_emb,
                       const float* __restrict__ sp_wr, const float* __restrict__ sp_br,
                       const float* __restrict__ sp_wi, const float* __restrict__ sp_bi) {
    int bc = blockIdx.x; int b = bc >> 6, c = bc & 63;
    int hc = c >> 4, oc = c & 15;
    int tid = threadIdx.x;
    __shared__ float2 Fm[MXY], Fs[MXY];
    __shared__ __align__(16) float2 Gm[128*18], Gs[128*18];
    __shared__ float2 twp[128];
    __shared__ float fes[EDF];
    __shared__ int s_fidx;
    for (int t = tid; t < 128; t += 256) {
        float s, co; sincospif(t * (1.0f/64.0f), &s, &co);
        twp[t] = make_float2(co, s);
    }
    if (tid == 0) {
        double msum = 0.0;
        const double* mp = g_magpart + b*CC;
        for (int i = 0; i < CC; i++) msum += mp[i];
        float mag = (float)(msum / (double)(CC*MXY));
        s_fidx = ((int)(mag * 1000.0f)) % NPF;
    }
    __syncthreads();
    if (tid < EDF) fes[tid] = sp_emb[s_fidx*EDF + tid];
    __syncthreads();

    const float2* lob = g_lo + b*CC*MXY;
    const float* wrb = wr + (size_t)(hc*CC*OPH + oc)*MXY;
    const float* wib = wi + (size_t)(hc*CC*OPH + oc)*MXY;
    for (int o = tid; o < MXY; o += 256) {
        float mr = 0.f, mi = 0.f;
        for (int i = 0; i < CC; i++) {
            float2 l = lob[i*MXY + o];
            float a = wrb[(size_t)i*OPH*MXY + o];
            float bb = wib[(size_t)i*OPH*MXY + o];
            mr += l.x*a - l.y*bb;
            mi += l.x*bb + l.y*a;
        }
        Fm[o] = make_float2(mr, mi);
        float sr = sp_br[c*MXY + o], si = sp_bi[c*MXY + o];
        for (int e = 0; e < EDF; e++) {
            float f = fes[e];
            sr += f * sp_wr[(size_t)e*(CC*MXY) + c*MXY + o];
            si += f * sp_wi[(size_t)e*(CC*MXY) + c*MXY + o];
        }
        Fs[o] = make_float2(sr, si);
    }
    __syncthreads();

    // stage G folded
    for (int o = tid; o < 33*17; o += 256) {
        int h = o/17, ky = o%17;
        ull Pme=0,Qme=0,Pmo=0,Qmo=0, Pse=0,Qse=0,Pso=0,Qso=0;
        int ti = 0;
        #pragma unroll 4
        for (int kx = 0; kx < MX; kx += 2) {
            {
                float2 e = twp[ti]; ti = (ti + h) & 127;
                ull ev = pk(e.x, e.y);
                float2 fm = Fm[kx*17 + ky], fs = Fs[kx*17 + ky];
                Pme = ffma2(pk(fm.x, fm.x), ev, Pme);
                Qme = ffma2(pk(fm.y, fm.y), ev, Qme);
                Pse = ffma2(pk(fs.x, fs.x), ev, Pse);
                Qse = ffma2(pk(fs.y, fs.y), ev, Qse);
            }
            {
                float2 e = twp[ti]; ti = (ti + h) & 127;
                ull ev = pk(e.x, e.y);
                float2 fm = Fm[(kx+1)*17 + ky], fs = Fs[(kx+1)*17 + ky];
                Pmo = ffma2(pk(fm.x, fm.x), ev, Pmo);
                Qmo = ffma2(pk(fm.y, fm.y), ev, Qmo);
                Pso = ffma2(pk(fs.x, fs.x), ev, Pso);
                Qso = ffma2(pk(fs.y, fs.y), ev, Qso);
            }
        }
        int slot = (ky & 1) ? (10 + (ky >> 1)) : (ky >> 1);
        float pex,pey,qex,qey,pox,poy,qox,qoy;
        #define G_EMIT(G, Pe, Qe, Po, Qo) \
            upk(Pe,pex,pey); upk(Qe,qex,qey); upk(Po,pox,poy); upk(Qo,qox,qoy); \
            { float Px=pex+pox, Py=pey+poy, Qx=qex+qox, Qy=qey+qoy; \
              float Mx=pex-pox, My=pey-poy, Nx=qex-qox, Ny=qey-qoy; \
              G[h*18 + slot]        = make_float2(Px - Qy, Py + Qx); \
              G[(h+64)*18 + slot]   = make_float2(Mx - Ny, My + Nx); \
              if (h) { \
                G[(128-h)*18 + slot] = make_float2(Px + Qy, Qx - Py); \
                G[(64-h)*18 + slot]  = make_float2(Mx + Ny, Nx - My); \
              } }
        G_EMIT(Gm, Pme, Qme, Pmo, Qmo)
        G_EMIT(Gs, Pse, Qse, Pso, Qso)
        #undef G_EMIT
    }
    __syncthreads();

    // stage B folded + gated combine: fused = gb*(m + bias) + gmw*s
    float bias = mhf_bias[c];
    float gb = g_gw[b*3 + 1], gmw = g_gw[b*3 + 2];
    const float sc = 0.0078125f;
    float* fout = g_fused + (size_t)bc*HW;
    {
        int w = tid & 31;
        int hg = tid >> 5;
        ull cse[9], cso[8];
        cse[0] = pk(1.f, 0.f);
        #pragma unroll
        for (int j = 1; j < 9; j++) {
            float2 e = twp[(2*j*w) & 127];
            cse[j] = pk(2.f*e.x, 2.f*e.y);
        }
        #pragma unroll
        for (int j = 0; j < 8; j++) {
            float2 e = twp[((2*j+1)*w) & 127];
            cso[j] = pk(2.f*e.x, 2.f*e.y);
        }
        for (int i = 0; i < 16; i++) {
            int h = hg*16 + i;
            const float4* Ge4m = (const float4*)(Gm + h*18);
            const float4* Go4m = (const float4*)(Gm + h*18 + 10);
            const float4* Ge4s = (const float4*)(Gs + h*18);
            const float4* Go4s = (const float4*)(Gs + h*18 + 10);
            ull me = 0, mo = 0, se = 0, so = 0;
            #pragma unroll
            for (int j2 = 0; j2 < 4; j2++) {
                float4 g = Ge4m[j2];
                me = ffma2(pk(g.x,g.y), cse[2*j2],   me);
                me = ffma2(pk(g.z,g.w), cse[2*j2+1], me);
                float4 s4 = Ge4s[j2];
                se = ffma2(pk(s4.x,s4.y), cse[2*j2],   se);
                se = ffma2(pk(s4.z,s4.w), cse[2*j2+1], se);
            }
            { float2 g = Gm[h*18 + 8]; me = ffma2(pk(g.x,g.y), cse[8], me);
              float2 s2 = Gs[h*18 + 8]; se = ffma2(pk(s2.x,s2.y), cse[8], se); }
            #pragma unroll
            for (int j2 = 0; j2 < 4; j2++) {
                float4 g = Go4m[j2];
                mo = ffma2(pk(g.x,g.y), cso[2*j2],   mo);
                mo = ffma2(pk(g.z,g.w), cso[2*j2+1], mo);
                float4 s4 = Go4s[j2];
                so = ffma2(pk(s4.x,s4.y), cso[2*j2],   so);
                so = ffma2(pk(s4.z,s4.w), cso[2*j2+1], so);
            }
            float Ae,Be,Ao,Bo, Ce,De,Co,Do;
            upk(me,Ae,Be); upk(mo,Ao,Bo);
            upk(se,Ce,De); upk(so,Co,Do);
            float apm=Ae+Ao, bpm=Be+Bo, amm=Ae-Ao, bmm=Be-Bo;
            float aps=Ce+Co, bps=De+Do, ams=Ce-Co, bms=De-Do;
            fout[h*WW + w]      = gb*((apm - bpm)*sc + bias) + gmw*((aps - bps)*sc);
            fout[h*WW + 64 + w] = gb*((amm - bmm)*sc + bias) + gmw*((ams - bms)*sc);
            if (w) {
                fout[h*WW + 128 - w] = gb*((apm + bpm)*sc + bias) + gmw*((aps + bps)*sc);
                fout[h*WW + 64 - w]  = gb*((amm + bmm)*sc + bias) + gmw*((ams + bms)*sc);
            }
        }
    }
    // w = 32 orbit {32, 96}
    if (tid < 128) {
        int h = tid;
        ull cse[9], cso[8];
        cse[0] = pk(1.f, 0.f);
        #pragma unroll
        for (int j = 1; j < 9; j++) {
            float2 e = twp[(2*j*32) & 127];
            cse[j] = pk(2.f*e.x, 2.f*e.y);
        }
        #pragma unroll
        for (int j = 0; j < 8; j++) {
            float2 e = twp[((2*j+1)*32) & 127];
            cso[j] = pk(2.f*e.x, 2.f*e.y);
        }
        const float4* Ge4m = (const float4*)(Gm + h*18);
        const float4* Go4m = (const float4*)(Gm + h*18 + 10);
        const float4* Ge4s = (const float4*)(Gs + h*18);
        const float4* Go4s = (const float4*)(Gs + h*18 + 10);
        ull me = 0, mo = 0, se = 0, so = 0;
        #pragma unroll
        for (int j2 = 0; j2 < 4; j2++) {
            float4 g = Ge4m[j2];
            me = ffma2(pk(g.x,g.y), cse[2*j2],   me);
            me = ffma2(pk(g.z,g.w), cse[2*j2+1], me);
            float4 s4 = Ge4s[j2];
            se = ffma2(pk(s4.x,s4.y), cse[2*j2],   se);
            se = ffma2(pk(s4.z,s4.w), cse[2*j2+1], se);
        }
        { float2 g = Gm[h*18 + 8]; me = ffma2(pk(g.x,g.y), cse[8], me);
          float2 s2 = Gs[h*18 + 8]; se = ffma2(pk(s2.x,s2.y), cse[8], se); }
        #pragma unroll
        for (int j2 = 0; j2 < 4; j2++) {
            float4 g = Go4m[j2];
            mo = ffma2(pk(g.x,g.y), cso[2*j2],   mo);
            mo = ffma2(pk(g.z,g.w), cso[2*j2+1], mo);
            float4 s4 = Go4s[j2];
            so = ffma2(pk(s4.x,s4.y), cso[2*j2],   so);
            so = ffma2(pk(s4.z,s4.w), cso[2*j2+1], so);
        }
        float Ae,Be,Ao,Bo, Ce,De,Co,Do;
        upk(me,Ae,Be); upk(mo,Ao,Bo);
        upk(se,Ce,De); upk(so,Co,Do);
        fout[h*WW + 32] = gb*(((Ae+Ao) - (Be+Bo))*sc + bias) + gmw*(((Ce+Co) - (De+Do))*sc);
        fout[h*WW + 96] = gb*(((Ae-Ao) - (Be-Bo))*sc + bias) + gmw*(((Ce-Co) - (De-Do))*sc);
    }
}

// y = ga*spatial + fused + skip conv + skip_b; accumulate LN stats
__global__ void k_y(const float* __restrict__ x,
                    const float* __restrict__ skip_w,
                    const float* __restrict__ skip_b) {
    int bx = blockIdx.x;
    int b = bx >> 8, tile = bx & 255;
    int pbase = tile * 64;
    int tid = threadIdx.x;
    __shared__ float buf[64*65];
    __shared__ float ys[64*64];
    __shared__ int idxs[64];
    __shared__ float sb[64];
    __shared__ float red[256], redq[256];

    if (tid < 64) idxs[tid] = g_idx[b*HW + pbase + tid];
    else if (tid < 128) sb[tid - 64] = skip_b[tid - 64];
    for (int o = tid; o < 4096; o += 256) {
        int i = o >> 6, p = o & 63;
        buf[i*64 + p] = x[((size_t)(b*64 + i))*HW + pbase + p];
    }
    __syncthreads();
    {
        int pg = tid & 15, cg = tid >> 4;
        ull acc[4][2];
        #pragma unroll
        for (int px = 0; px < 4; px++) { acc[px][0] = 0; acc[px][1] = 0; }
        for (int i = 0; i < 64; i++) {
            float4 xv = *(const float4*)(buf + i*64 + pg*4);
            ull x0 = pk(xv.x, xv.x), x1 = pk(xv.y, xv.y),
                x2 = pk(xv.z, xv.z), x3 = pk(xv.w, xv.w);
            float4 wv = __ldg((const float4*)(skip_w + i*64 + cg*4));
            ull wA = pk(wv.x, wv.y), wB = pk(wv.z, wv.w);
            acc[0][0] = ffma2(x0, wA, acc[0][0]); acc[0][1] = ffma2(x0, wB, acc[0][1]);
            acc[1][0] = ffma2(x1, wA, acc[1][0]); acc[1][1] = ffma2(x1, wB, acc[1][1]);
            acc[2][0] = ffma2(x2, wA, acc[2][0]); acc[2][1] = ffma2(x2, wB, acc[2][1]);
            acc[3][0] = ffma2(x3, wA, acc[3][0]); acc[3][1] = ffma2(x3, wB, acc[3][1]);
        }
        #pragma unroll
        for (int px = 0; px < 4; px++) {
            int p = pg*4 + px;
            #pragma unroll
            for (int u = 0; u < 2; u++) {
                float v0, v1; upk(acc[px][u], v0, v1);
                ys[(cg*4 + 2*u    )*64 + p] = v0;
                ys[(cg*4 + 2*u + 1)*64 + p] = v1;
            }
        }
    }
    __syncthreads();
    // prefetch fused plane values (MLP 16) while doing the table gather
    float fv[16];
    #pragma unroll
    for (int it = 0; it < 16; it++) {
        int o = tid + it*256;
        int cch = o >> 6, p = o & 63;
        fv[it] = g_fused[((size_t)(b*64 + cch))*HW + pbase + p];
    }
    for (int o = tid; o < 4096; o += 256) {
        int p = o >> 6, cc2 = o & 63;
        buf[p*65 + cc2] = g_table[idxs[p]*CC + cc2];
    }
    __syncthreads();
    float ga = g_gw[b*3];
    float lsum = 0.f, lsq = 0.f;
    #pragma unroll
    for (int it = 0; it < 16; it++) {
        int o = tid + it*256;
        int cch = o >> 6, p = o & 63;
        size_t gidx = ((size_t)(b*64 + cch))*HW + pbase + p;
        float yv = ga*buf[p*65 + cch] + fv[it] + ys[cch*64 + p] + sb[cch];
        g_y[gidx] = yv;
        lsum += yv; lsq += yv*yv;
    }
    red[tid] = lsum; redq[tid] = lsq; __syncthreads();
    for (int s = 128; s > 0; s >>= 1) {
        if (tid < s) { red[tid] += red[tid+s]; redq[tid] += redq[tid+s]; }
        __syncthreads();
    }
    if (tid == 0) {
        atomicAdd(&g_ysum[b], (double)red[0]);
        atomicAdd(&g_ysq[b],  (double)redq[0]);
    }
}

// layernorm + MLP + residual; y tile staged in smem
__global__ void k_mlp(const float* __restrict__ norm_g, const float* __restrict__ norm_b,
                      const float* __restrict__ w1, const float* __restrict__ b1,
                      const float* __restrict__ w2, const float* __restrict__ b2,
                      float* __restrict__ out) {
    extern __shared__ float sm[];
    float* w12 = sm;                        // 8192
    float* yns = sm + 8192;                 // 4096
    float* hs  = sm + 8192 + 4096;          // 8192
    float* yt  = sm + 8192 + 4096 + 8192;   // 4096: raw y tile
    __shared__ float s_mu, s_rstd;
    int bx = blockIdx.x;
    int b = bx >> 8, tile = bx & 255;
    int pbase = tile * 64;
    int tid = threadIdx.x;

    if (tid == 0) {
        double n = (double)(CC*HW);
        double mu = g_ysum[b] / n;
        double var = g_ysq[b] / n - mu*mu;
        s_mu = (float)mu;
        s_rstd = (float)(1.0 / sqrt(var + 1e-5));
    }
    for (int o = tid; o < 8192; o += 256) w12[o] = w1[o];
    __syncthreads();
    float mu = s_mu, rstd = s_rstd;
    for (int o = tid; o < 4096; o += 256) {
        int c = o >> 6, p = o & 63;
        float yv = g_y[((size_t)(b*64 + c))*HW + pbase + p];
        yt[c*64 + p] = yv;
        yns[c*64 + p] = (yv - mu)*rstd*norm_g[c] + norm_b[c];
    }
    __syncthreads();
    {
        int pg = tid & 15, jg = tid >> 4;
        ull acc[4][4];
        #pragma unroll
        for (int px = 0; px < 4; px++)
            #pragma unroll
            for (int u = 0; u < 4; u++) acc[px][u] = 0;
        for (int c = 0; c < 64; c++) {
            float4 yv4 = *(const float4*)(yns + c*64 + pg*4);
            ull y0 = pk(yv4.x, yv4.x), y1 = pk(yv4.y, yv4.y),
                y2 = pk(yv4.z, yv4.z), y3 = pk(yv4.w, yv4.w);
            const float4* wrow = (const float4*)(w12 + c*128 + jg*8);
            float4 wa = wrow[0], wb = wrow[1];
            ull w0 = pk(wa.x, wa.y), w1p = pk(wa.z, wa.w),
                w2p = pk(wb.x, wb.y), w3 = pk(wb.z, wb.w);
            acc[0][0] = ffma2(y0, w0, acc[0][0]); acc[0][1] = ffma2(y0, w1p, acc[0][1]);
            acc[0][2] = ffma2(y0, w2p, acc[0][2]); acc[0][3] = ffma2(y0, w3, acc[0][3]);
            acc[1][0] = ffma2(y1, w0, acc[1][0]); acc[1][1] = ffma2(y1, w1p, acc[1][1]);
            acc[1][2] = ffma2(y1, w2p, acc[1][2]); acc[1][3] = ffma2(y1, w3, acc[1][3]);
            acc[2][0] = ffma2(y2, w0, acc[2][0]); acc[2][1] = ffma2(y2, w1p, acc[2][1]);
            acc[2][2] = ffma2(y2, w2p, acc[2][2]); acc[2][3] = ffma2(y2, w3, acc[2][3]);
            acc[3][0] = ffma2(y3, w0, acc[3][0]); acc[3][1] = ffma2(y3, w1p, acc[3][1]);
            acc[3][2] = ffma2(y3, w2p, acc[3][2]); acc[3][3] = ffma2(y3, w3, acc[3][3]);
        }
        int j0 = jg*8;
        #pragma unroll
        for (int px = 0; px < 4; px++) {
            int p = pg*4 + px;
            #pragma unroll
            for (int u = 0; u < 4; u++) {
                float v0, v1; upk(acc[px][u], v0, v1);
                int j = j0 + 2*u;
                float a0 = v0 + b1[j], a1 = v1 + b1[j+1];
                hs[j*64 + p]     = 0.5f*a0*(1.0f + erff(a0*0.70710678118654752f));
                hs[(j+1)*64 + p] = 0.5f*a1*(1.0f + erff(a1*0.70710678118654752f));
            }
        }
    }
    __syncthreads();
    for (int o = tid; o < 8192; o += 256) w12[o] = w2[o];
    __syncthreads();
    {
        int pg = tid & 15, cg = tid >> 4;
        ull acc2[4][2];
        #pragma unroll
        for (int px = 0; px < 4; px++) { acc2[px][0] = 0; acc2[px][1] = 0; }
        for (int j = 0; j < 128; j++) {
            float4 hv4 = *(const float4*)(hs + j*64 + pg*4);
            ull h0 = pk(hv4.x, hv4.x), h1 = pk(hv4.y, hv4.y),
                h2 = pk(hv4.z, hv4.z), h3 = pk(hv4.w, hv4.w);
            float4 wv = *(const float4*)(w12 + j*64 + cg*4);
            ull wA = pk(wv.x, wv.y), wB = pk(wv.z, wv.w);
            acc2[0][0] = ffma2(h0, wA, acc2[0][0]); acc2[0][1] = ffma2(h0, wB, acc2[0][1]);
            acc2[1][0] = ffma2(h1, wA, acc2[1][0]); acc2[1][1] = ffma2(h1, wB, acc2[1][1]);
            acc2[2][0] = ffma2(h2, wA, acc2[2][0]); acc2[2][1] = ffma2(h2, wB, acc2[2][1]);
            acc2[3][0] = ffma2(h3, wA, acc2[3][0]); acc2[3][1] = ffma2(h3, wB, acc2[3][1]);
        }
        __syncthreads();
        #pragma unroll
        for (int px = 0; px < 4; px++) {
            int p = pg*4 + px;
            #pragma unroll
            for (int u = 0; u < 2; u++) {
                float v0, v1; upk(acc2[px][u], v0, v1);
                yns[(cg*4 + 2*u    )*64 + p] = v0;
                yns[(cg*4 + 2*u + 1)*64 + p] = v1;
            }
        }
    }
    __syncthreads();
    for (int o = tid; o < 4096; o += 256) {
        int c = o >> 6, p = o & 63;
        size_t gi2 = ((size_t)(b*64 + c))*HW + pbase + p;
        out[gi2] = yt[c*64 + p] + yns[c*64 + p] + b2[c];
    }
}

// ---------------------------------------------------------------------------
extern "C" void kernel_launch(void* const* d_in, const int* in_sizes, int n_in,
                              void* d_out, int out_size) {
    const float* x        = (const float*)d_in[0];
    const float* se_emb   = (const float*)d_in[1];
    const float* se_w     = (const float*)d_in[2];
    const float* se_b     = (const float*)d_in[3];
    const float* mhf_wr   = (const float*)d_in[4];
    const float* mhf_wi   = (const float*)d_in[5];
    const float* mhf_bias = (const float*)d_in[6];
    const float* sp_emb   = (const float*)d_in[7];
    const float* sp_wr    = (const float*)d_in[8];
    const float* sp_br    = (const float*)d_in[9];
    const float* sp_wi    = (const float*)d_in[10];
    const float* sp_bi    = (const float*)d_in[11];
    const float* gate_w1  = (const float*)d_in[12];
    const float* gate_b1  = (const float*)d_in[13];
    const float* gate_w2  = (const float*)d_in[14];
    const float* gate_b2  = (const float*)d_in[15];
    const float* skip_w   = (const float*)d_in[16];
    const float* skip_b   = (const float*)d_in[17];
    const float* norm_g   = (const float*)d_in[18];
    const float* norm_b   = (const float*)d_in[19];
    const float* mlp_w1   = (const float*)d_in[20];
    const float* mlp_b1   = (const float*)d_in[21];
    const float* mlp_w2   = (const float*)d_in[22];
    const float* mlp_b2   = (const float*)d_in[23];
    float* out = (float*)d_out;

    cudaFuncSetAttribute(k_fwd, cudaFuncAttributeMaxDynamicSharedMemorySize, FWD_SMEM);
    cudaFuncSetAttribute(k_mlp, cudaFuncAttributeMaxDynamicSharedMemorySize, MLP_SMEM);

    k_table<<<(NPS*16 + 255)/256, 256>>>(se_emb, se_w, se_b);
    k_hash<<<BB*HH, 128>>>(x);
    k_fwd<<<BB*CC, 256, FWD_SMEM>>>(x);
    k_spat<<<BB*SPART, 128>>>();
    k_pre<<<BB, 64>>>(mhf_wr, mhf_wi, mhf_bias, sp_emb, sp_wr, sp_br);
    k_gate<<<1, 512>>>(gate_w1, gate_b1, gate_w2, gate_b2);
    k_coef<<<BB*CC, 256>>>(mhf_wr, mhf_wi, mhf_bias, sp_emb, sp_wr, sp_br, sp_wi, sp_bi);
    k_y<<<BB*256, 256>>>(x, skip_w, skip_b);
    k_mlp<<<BB*256, 256, MLP_SMEM>>>(norm_g, norm_b, mlp_w1, mlp_b1, mlp_w2, mlp_b2, out);
}